// round 1
// baseline (speedup 1.0000x reference)
#include <cuda_runtime.h>
#include <cuda_bf16.h>

#define N_NODES 50000
#define N_EDGES 800000
#define D_IN    96
#define D_EDGE  32
#define D_OUT   96
#define N_TYPES 4

// Scratch: y[t][n][j] = 0.25 * (x[n] @ W_x[t] + b[t])   (76.8 MB)
__device__ float g_y[(size_t)N_TYPES * N_NODES * D_OUT];

// ---------------------------------------------------------------------------
// Kernel A: per-(node,type) precompute of the x-part + bias, scaled by 1/4.
// Grid: (ceil(N/64), 4). Block: 256 threads (8 warps, 8 nodes/warp).
// ---------------------------------------------------------------------------
__global__ __launch_bounds__(256) void precompute_y_kernel(
    const float* __restrict__ x,      // [N, 96]
    const float* __restrict__ W,      // [4, 128, 96]
    const float* __restrict__ b)      // [4, 96]
{
    const int t     = blockIdx.y;
    const int node0 = blockIdx.x * 64;

    __shared__ float Wsm[D_IN][D_OUT];   // 96x96 = 36 KB (rows 0..95 of W[t])
    __shared__ float xs[64][D_IN];       // 24 KB
    __shared__ float bsm[D_OUT];

    const float* Wt = W + (size_t)t * 128 * 96;
    for (int i = threadIdx.x; i < D_IN * D_OUT; i += blockDim.x)
        (&Wsm[0][0])[i] = 0.25f * Wt[i];
    if (threadIdx.x < D_OUT)
        bsm[threadIdx.x] = 0.25f * b[t * D_OUT + threadIdx.x];
    for (int i = threadIdx.x; i < 64 * D_IN; i += blockDim.x) {
        int r = i / D_IN, c = i - r * D_IN;
        int n = node0 + r;
        (&xs[0][0])[i] = (n < N_NODES) ? x[(size_t)n * D_IN + c] : 0.0f;
    }
    __syncthreads();

    const int wid  = threadIdx.x >> 5;
    const int lane = threadIdx.x & 31;
    const int i0   = wid * 8;

    float acc[8][3];
    float b0 = bsm[lane], b1 = bsm[lane + 32], b2 = bsm[lane + 64];
#pragma unroll
    for (int i = 0; i < 8; i++) { acc[i][0] = b0; acc[i][1] = b1; acc[i][2] = b2; }

#pragma unroll 4
    for (int k = 0; k < D_IN; k++) {
        float w0 = Wsm[k][lane];
        float w1 = Wsm[k][lane + 32];
        float w2 = Wsm[k][lane + 64];
#pragma unroll
        for (int i = 0; i < 8; i++) {
            float xv = xs[i0 + i][k];
            acc[i][0] = fmaf(xv, w0, acc[i][0]);
            acc[i][1] = fmaf(xv, w1, acc[i][1]);
            acc[i][2] = fmaf(xv, w2, acc[i][2]);
        }
    }

#pragma unroll
    for (int i = 0; i < 8; i++) {
        int n = node0 + i0 + i;
        if (n < N_NODES) {
            float* yp = g_y + ((size_t)t * N_NODES + n) * D_OUT;
            yp[lane]      = acc[i][0];
            yp[lane + 32] = acc[i][1];
            yp[lane + 64] = acc[i][2];
        }
    }
}

// ---------------------------------------------------------------------------
// Kernel B: edge kernel. Each block handles one relation type (blockIdx.y).
// Warps scan their edge range, compact matching edges into a per-warp queue
// (ballot + rank), then process them in same-type batches of 8 so the
// smem-cached W_e row load amortizes over 24 FMAs.
// out[dst] += y[t][src] + 0.25 * (|ef[src]-ef[dst]| @ W_e[t])
// ---------------------------------------------------------------------------
#define EK_WARPS 8
#define BATCH    8
#define QCAP     40   // queue max fill: <8 leftover + 32 newly scanned

__global__ __launch_bounds__(256) void edge_kernel(
    const float* __restrict__ ef,     // [N, 32]
    const int*   __restrict__ src,    // [E]
    const int*   __restrict__ dst,    // [E]
    const int*   __restrict__ et,     // [E]
    const float* __restrict__ W,      // [4, 128, 96]
    float*       __restrict__ out)    // [N, 96]
{
    const int t = blockIdx.y;

    __shared__ float Wsm[D_EDGE][D_OUT];                  // 12 KB
    __shared__ int   eidx[EK_WARPS][QCAP];
    __shared__ float esm[EK_WARPS][BATCH][D_EDGE];        // 8 KB

    // rows 96..127 of W[t] = W_e, pre-scaled by 1/4
    const float* Wt = W + (size_t)t * 128 * 96 + 96 * 96;
    for (int i = threadIdx.x; i < D_EDGE * D_OUT; i += blockDim.x)
        (&Wsm[0][0])[i] = 0.25f * Wt[i];
    __syncthreads();

    const int wid  = threadIdx.x >> 5;
    const int lane = threadIdx.x & 31;
    const unsigned lanemask_lt = (1u << lane) - 1u;

    const long gw     = (long)blockIdx.x * EK_WARPS + wid;
    const long stride = (long)gridDim.x * EK_WARPS * 32;

    long base = gw * 32;
    int  q    = 0;

    while (true) {
        // refill queue until >= BATCH matching edges (or edges exhausted)
        while (q < BATCH && base < N_EDGES) {
            long eid = base + lane;
            bool ok  = (eid < N_EDGES) && (et[eid] == t);
            unsigned m = __ballot_sync(0xffffffffu, ok);
            int rank = __popc(m & lanemask_lt);
            if (ok) eidx[wid][q + rank] = (int)eid;
            q    += __popc(m);
            base += stride;
        }
        __syncwarp();
        if (q == 0) break;

        const int B = (q < BATCH) ? q : BATCH;   // warp-uniform

        int   s[BATCH], d[BATCH];
        float acc[BATCH][3];
#pragma unroll
        for (int i = 0; i < BATCH; i++) {
            bool v = (i < B);
            int e2 = v ? eidx[wid][i] : eidx[wid][0];
            s[i] = src[e2];
            d[i] = dst[e2];
            float a  = ef[(size_t)s[i] * D_EDGE + lane];
            float bb = ef[(size_t)d[i] * D_EDGE + lane];
            esm[wid][i][lane] = fabsf(a - bb);
            const float* yp = g_y + ((size_t)t * N_NODES + s[i]) * D_OUT;
            acc[i][0] = yp[lane];
            acc[i][1] = yp[lane + 32];
            acc[i][2] = yp[lane + 64];
        }
        __syncwarp();

#pragma unroll 4
        for (int k = 0; k < D_EDGE; k++) {
            float w0 = Wsm[k][lane];
            float w1 = Wsm[k][lane + 32];
            float w2 = Wsm[k][lane + 64];
#pragma unroll
            for (int i = 0; i < BATCH; i++) {
                float ev = esm[wid][i][k];
                acc[i][0] = fmaf(ev, w0, acc[i][0]);
                acc[i][1] = fmaf(ev, w1, acc[i][1]);
                acc[i][2] = fmaf(ev, w2, acc[i][2]);
            }
        }

#pragma unroll
        for (int i = 0; i < BATCH; i++) {
            if (i < B) {
                float* op = out + (size_t)d[i] * D_OUT;
                atomicAdd(op + lane,      acc[i][0]);
                atomicAdd(op + lane + 32, acc[i][1]);
                atomicAdd(op + lane + 64, acc[i][2]);
            }
        }

        // slide remainder (<8 after full batches) to queue front
        int rem = q - B;
        int tmp = 0;
        __syncwarp();
        if (lane < rem) tmp = eidx[wid][B + lane];
        __syncwarp();
        if (lane < rem) eidx[wid][lane] = tmp;
        __syncwarp();
        q = rem;
    }
}

// ---------------------------------------------------------------------------
extern "C" void kernel_launch(void* const* d_in, const int* in_sizes, int n_in,
                              void* d_out, int out_size)
{
    const float* x   = (const float*)d_in[0];          // [N, 96]
    const float* ef  = (const float*)d_in[1];          // [N, 32]
    const int*   ei  = (const int*)  d_in[2];          // [2, E]
    const int*   et  = (const int*)  d_in[3];          // [E]
    const float* W   = (const float*)d_in[4];          // [4, 128, 96]
    const float* b   = (const float*)d_in[5];          // [4, 96]
    float*       out = (float*)d_out;                  // [N, 96]

    const int* src = ei;
    const int* dst = ei + N_EDGES;

    cudaMemsetAsync(out, 0, (size_t)out_size * sizeof(float), 0);

    {
        dim3 grid((N_NODES + 63) / 64, N_TYPES);
        precompute_y_kernel<<<grid, 256>>>(x, W, b);
    }
    {
        dim3 grid(296, N_TYPES);
        edge_kernel<<<grid, 256>>>(ef, src, dst, et, W, out);
    }
}